// round 1
// baseline (speedup 1.0000x reference)
#include <cuda_runtime.h>
#include <cuda_bf16.h>
#include <math.h>

// Problem sizes (fixed by the dataset)
#define NB   128
#define RDIM 2304
#define CDIM 256
#define MAT  (RDIM * CDIM)   // 589824
#define CMAT (CDIM * CDIM)   // 65536

// GEMM tiling
#define BM 128
#define BN 128
#define BK 16
#define SST 132   // smem row stride (padded, float4-aligned)

// Scratch layout inside one big __device__ array (no cudaMalloc allowed):
//   A   : [NB][CMAT]   (M^T G, then symmetrized in place)
//   Y   : [NB][MAT]    (M + P)
//   Bm  : [NB][CMAT]   (Y^T Y)
//   X   : [NB][CMAT]   (R^{-1}, dense upper triangular)
#define OFF_A 0
#define OFF_Y ((size_t)CMAT * NB)
#define OFF_B (OFF_Y + (size_t)MAT * NB)
#define OFF_X (OFF_B + (size_t)CMAT * NB)
#define SCRATCH_FLOATS (OFF_X + (size_t)CMAT * NB)

__device__ float g_scratch[SCRATCH_FLOATS];

// ---------------------------------------------------------------------------
// Shared-memory tile loaders
// ---------------------------------------------------------------------------

// Load a [BK x 128] tile where K runs along matrix rows (operand stored
// "K-major": element (k, c) at g[k*CDIM + c]).  float4 along c -> coalesced.
__device__ __forceinline__ void load_k_major(float S[BK][SST], const float* g,
                                             int kt, int c0, int tid) {
    int c4 = (tid & 31) << 2;   // 0..124
    int kk = tid >> 5;          // 0..7
#pragma unroll
    for (int it = 0; it < 2; ++it) {
        float4 v = *reinterpret_cast<const float4*>(
            g + (size_t)(kt + kk + it * 8) * CDIM + c0 + c4);
        *reinterpret_cast<float4*>(&S[kk + it * 8][c4]) = v;
    }
}

// Load a [128 x BK] row-major tile (element (r, k) at g[r*CDIM + k]) and
// transpose into S[k][r].  float4 along k -> coalesced (64B chunks).
__device__ __forceinline__ void load_row_major_T(float S[BK][SST], const float* g,
                                                 int r0, int kt, int tid) {
    int k4 = (tid & 3) << 2;    // 0,4,8,12
    int rr = tid >> 2;          // 0..63
#pragma unroll
    for (int it = 0; it < 2; ++it) {
        int r = rr + it * 64;
        float4 v = *reinterpret_cast<const float4*>(
            g + (size_t)(r0 + r) * CDIM + kt + k4);
        S[k4 + 0][r] = v.x;
        S[k4 + 1][r] = v.y;
        S[k4 + 2][r] = v.z;
        S[k4 + 3][r] = v.w;
    }
}

// One BK-deep 128x128 MMA step; 8x8 per thread in two 4-wide halves (split
// layout keeps LDS.128 conflict-free: 16 consecutive lanes read 16
// consecutive float4s).
__device__ __forceinline__ void mma_step(float acc[8][8],
                                         const float SA[BK][SST],
                                         const float SB[BK][SST],
                                         int tx, int ty) {
#pragma unroll
    for (int kk = 0; kk < BK; ++kk) {
        float a[8], b[8];
        *reinterpret_cast<float4*>(&a[0]) = *reinterpret_cast<const float4*>(&SA[kk][tx * 4]);
        *reinterpret_cast<float4*>(&a[4]) = *reinterpret_cast<const float4*>(&SA[kk][tx * 4 + 64]);
        *reinterpret_cast<float4*>(&b[0]) = *reinterpret_cast<const float4*>(&SB[kk][ty * 4]);
        *reinterpret_cast<float4*>(&b[4]) = *reinterpret_cast<const float4*>(&SB[kk][ty * 4 + 64]);
#pragma unroll
        for (int i = 0; i < 8; ++i)
#pragma unroll
            for (int j = 0; j < 8; ++j)
                acc[i][j] += a[i] * b[j];
    }
}

// ---------------------------------------------------------------------------
// GEMM 1 & 3:  O[p,q] = sum_r P[r,p] * Q[r,q]   (256x256 out, K = 2304)
// Used for A = M^T G and Bm = Y^T Y.
// ---------------------------------------------------------------------------
__global__ __launch_bounds__(256) void gemm_AtB_kernel(const float* __restrict__ Pg,
                                                       const float* __restrict__ Qg,
                                                       float* __restrict__ Og) {
    __shared__ float SA[BK][SST];
    __shared__ float SB[BK][SST];
    int b = blockIdx.z;
    const float* P = Pg + (size_t)b * MAT;
    const float* Q = Qg + (size_t)b * MAT;
    float* O = Og + (size_t)b * CMAT;
    int p0 = blockIdx.y * BM, q0 = blockIdx.x * BN;
    int tid = threadIdx.x, tx = tid & 15, ty = tid >> 4;
    float acc[8][8] = {};
    for (int kt = 0; kt < RDIM; kt += BK) {
        load_k_major(SA, P, kt, p0, tid);
        load_k_major(SB, Q, kt, q0, tid);
        __syncthreads();
        mma_step(acc, SA, SB, tx, ty);
        __syncthreads();
    }
#pragma unroll
    for (int ih = 0; ih < 2; ++ih)
#pragma unroll
        for (int i = 0; i < 4; ++i) {
            int p = p0 + ih * 64 + tx * 4 + i;
#pragma unroll
            for (int jh = 0; jh < 2; ++jh) {
                float4 v = make_float4(acc[ih * 4 + i][jh * 4 + 0],
                                       acc[ih * 4 + i][jh * 4 + 1],
                                       acc[ih * 4 + i][jh * 4 + 2],
                                       acc[ih * 4 + i][jh * 4 + 3]);
                *reinterpret_cast<float4*>(&O[(size_t)p * CDIM + q0 + jh * 64 + ty * 4]) = v;
            }
        }
}

// ---------------------------------------------------------------------------
// Symmetrize A in place: A <- 0.5 * (A + A^T)
// ---------------------------------------------------------------------------
__global__ void sym_kernel(float* __restrict__ Ag) {
    float* A = Ag + (size_t)blockIdx.y * CMAT;
    int idx = blockIdx.x * blockDim.x + threadIdx.x;   // 0 .. 65535
    int i = idx >> 8, j = idx & 255;
    if (i < j) {
        float u = A[i * CDIM + j];
        float v = A[j * CDIM + i];
        float m = 0.5f * (u + v);
        A[i * CDIM + j] = m;
        A[j * CDIM + i] = m;
    }
}

// ---------------------------------------------------------------------------
// GEMM 2:  Y[r,c] = M[r,c] - beta*(U[r,c]+G[r,c]) + beta * sum_k M[r,k]*Asym[k,c]
// beta = |lr_b| * s_lr
// ---------------------------------------------------------------------------
__global__ __launch_bounds__(256) void gemm_Y_kernel(const float* __restrict__ Mg,
                                                     const float* __restrict__ Gg,
                                                     const float* __restrict__ Ug,
                                                     const float* __restrict__ lrg,
                                                     const float* __restrict__ slrg,
                                                     const float* __restrict__ Ag,
                                                     float* __restrict__ Yg) {
    __shared__ float SA[BK][SST];
    __shared__ float SB[BK][SST];
    int b = blockIdx.z;
    const float* M = Mg + (size_t)b * MAT;
    const float* G = Gg + (size_t)b * MAT;
    const float* U = Ug + (size_t)b * MAT;
    const float* Asym = Ag + (size_t)b * CMAT;
    float* Y = Yg + (size_t)b * MAT;
    int r0 = blockIdx.y * BM, c0 = blockIdx.x * BN;
    int tid = threadIdx.x, tx = tid & 15, ty = tid >> 4;
    float acc[8][8] = {};
    for (int kt = 0; kt < CDIM; kt += BK) {
        load_row_major_T(SA, M, r0, kt, tid);
        load_k_major(SB, Asym, kt, c0, tid);
        __syncthreads();
        mma_step(acc, SA, SB, tx, ty);
        __syncthreads();
    }
    float beta = fabsf(lrg[b]) * slrg[0];
#pragma unroll
    for (int ih = 0; ih < 2; ++ih)
#pragma unroll
        for (int i = 0; i < 4; ++i) {
            size_t r = (size_t)(r0 + ih * 64 + tx * 4 + i);
#pragma unroll
            for (int jh = 0; jh < 2; ++jh) {
                size_t base = r * CDIM + c0 + jh * 64 + ty * 4;
                float4 m = *reinterpret_cast<const float4*>(&M[base]);
                float4 g = *reinterpret_cast<const float4*>(&G[base]);
                float4 u = *reinterpret_cast<const float4*>(&U[base]);
                float4 o;
                o.x = m.x - beta * (u.x + g.x) + beta * acc[ih * 4 + i][jh * 4 + 0];
                o.y = m.y - beta * (u.y + g.y) + beta * acc[ih * 4 + i][jh * 4 + 1];
                o.z = m.z - beta * (u.z + g.z) + beta * acc[ih * 4 + i][jh * 4 + 2];
                o.w = m.w - beta * (u.w + g.w) + beta * acc[ih * 4 + i][jh * 4 + 3];
                *reinterpret_cast<float4*>(&Y[base]) = o;
            }
        }
}

// ---------------------------------------------------------------------------
// Cholesky (upper, positive diag) of Bm = R^T R, then X = R^{-1} (dense upper).
// One block (256 threads) per batch item; packed upper triangle in 128.5 KB smem.
// ---------------------------------------------------------------------------
__global__ __launch_bounds__(256) void cholinv_kernel(const float* __restrict__ Bg,
                                                      float* __restrict__ Xg) {
    extern __shared__ float sU[];   // packed upper: (i,j) i<=j at off(i) + j-i
    int b = blockIdx.x;
    const float* Bm = Bg + (size_t)b * CMAT;
    float* Xm = Xg + (size_t)b * CMAT;
    int tid = threadIdx.x;
    // load packed upper triangle
    for (int i = 0; i < CDIM; ++i) {
        int o = i * CDIM - (i * (i - 1)) / 2;
        for (int j = i + tid; j < CDIM; j += 256)
            sU[o + (j - i)] = Bm[i * CDIM + j];
    }
    __syncthreads();
    int lane = tid & 31, warp = tid >> 5;
    // right-looking Cholesky
    for (int k = 0; k < CDIM; ++k) {
        int ok = k * CDIM - (k * (k - 1)) / 2;
        float inv = rsqrtf(sU[ok]);     // all threads read before any write
        __syncthreads();
        for (int j = k + tid; j < CDIM; j += 256)
            sU[ok + (j - k)] *= inv;    // diag becomes sqrt(d), row scaled
        __syncthreads();
        for (int i = k + 1 + warp; i < CDIM; i += 8) {
            float rki = sU[ok + (i - k)];
            int oi = i * CDIM - (i * (i - 1)) / 2;
            for (int j = i + lane; j < CDIM; j += 32)
                sU[oi + (j - i)] -= rki * sU[ok + (j - k)];
        }
        __syncthreads();
    }
    // triangular inverse: thread j owns column j of X = R^{-1}
    {
        int j = tid;
        float x[CDIM];
        int oj = j * CDIM - (j * (j - 1)) / 2;
        x[j] = 1.0f / sU[oj];
        for (int i = j - 1; i >= 0; --i) {
            int oi = i * CDIM - (i * (i - 1)) / 2;
            float s = 0.0f;
            for (int k = i + 1; k <= j; ++k)
                s += sU[oi + (k - i)] * x[k];
            x[i] = -s / sU[oi];
        }
        for (int i = 0; i < CDIM; ++i)
            Xm[(size_t)i * CDIM + j] = (i <= j) ? x[i] : 0.0f;
    }
}

// ---------------------------------------------------------------------------
// GEMM 4:  out[c,r] = sum_{k<=c} Y[r,k] * X[k,c]   (transposed store)
// Triangular X lets us skip k-tiles above the column tile.
// ---------------------------------------------------------------------------
__global__ __launch_bounds__(256) void gemm_QT_kernel(const float* __restrict__ Yg,
                                                      const float* __restrict__ Xg,
                                                      float* __restrict__ outg) {
    __shared__ float SA[BK][SST];
    __shared__ float SB[BK][SST];
    int b = blockIdx.z;
    const float* Y = Yg + (size_t)b * MAT;
    const float* X = Xg + (size_t)b * CMAT;
    float* O = outg + (size_t)b * MAT;   // [CDIM][RDIM]
    int r0 = blockIdx.y * BM, c0 = blockIdx.x * BN;
    int tid = threadIdx.x, tx = tid & 15, ty = tid >> 4;
    float acc[8][8] = {};
    int kmax = c0 + BN;   // X[k,c] == 0 for k > c
    for (int kt = 0; kt < kmax; kt += BK) {
        load_row_major_T(SA, Y, r0, kt, tid);
        load_k_major(SB, X, kt, c0, tid);
        __syncthreads();
        mma_step(acc, SA, SB, tx, ty);
        __syncthreads();
    }
#pragma unroll
    for (int jh = 0; jh < 2; ++jh)
#pragma unroll
        for (int j = 0; j < 4; ++j) {
            size_t c = (size_t)(c0 + jh * 64 + ty * 4 + j);
#pragma unroll
            for (int ih = 0; ih < 2; ++ih) {
                float4 v = make_float4(acc[ih * 4 + 0][jh * 4 + j],
                                       acc[ih * 4 + 1][jh * 4 + j],
                                       acc[ih * 4 + 2][jh * 4 + j],
                                       acc[ih * 4 + 3][jh * 4 + j]);
                *reinterpret_cast<float4*>(&O[c * RDIM + r0 + ih * 64 + tx * 4]) = v;
            }
        }
}

// ---------------------------------------------------------------------------
// Launch
// ---------------------------------------------------------------------------
extern "C" void kernel_launch(void* const* d_in, const int* in_sizes, int n_in,
                              void* d_out, int out_size) {
    const float* M   = (const float*)d_in[0];
    const float* G   = (const float*)d_in[1];
    const float* U   = (const float*)d_in[2];
    const float* lr  = (const float*)d_in[3];
    const float* slr = (const float*)d_in[4];
    float* out = (float*)d_out;

    float* scratch = nullptr;
    cudaGetSymbolAddress((void**)&scratch, g_scratch);
    float* A  = scratch + OFF_A;
    float* Y  = scratch + OFF_Y;
    float* Bm = scratch + OFF_B;
    float* X  = scratch + OFF_X;

    const int TRI_BYTES = (CDIM * (CDIM + 1) / 2) * (int)sizeof(float);  // 131584
    cudaFuncSetAttribute(cholinv_kernel,
                         cudaFuncAttributeMaxDynamicSharedMemorySize, TRI_BYTES);

    // 1) A = M^T G
    gemm_AtB_kernel<<<dim3(2, 2, NB), 256>>>(M, G, A);
    // 2) A <- sym(A)
    sym_kernel<<<dim3(CMAT / 256, NB), 256>>>(A);
    // 3) Y = M - beta*(U+G) + beta*M*Asym
    gemm_Y_kernel<<<dim3(2, RDIM / BM, NB), 256>>>(M, G, U, lr, slr, A, Y);
    // 4) Bm = Y^T Y
    gemm_AtB_kernel<<<dim3(2, 2, NB), 256>>>(Y, Y, Bm);
    // 5) R = chol(Bm), X = R^{-1}
    cholinv_kernel<<<NB, 256, TRI_BYTES>>>(Bm, X);
    // 6) out = (Y X)^T
    gemm_QT_kernel<<<dim3(2, RDIM / BM, NB), 256>>>(Y, X, out);
}

// round 16
// speedup vs baseline: 1.5433x; 1.5433x over previous
#include <cuda_runtime.h>
#include <cuda_bf16.h>
#include <math.h>
#include <stdint.h>

// Problem sizes (fixed by the dataset)
#define NB   128
#define RDIM 2304
#define CDIM 256
#define MAT  (RDIM * CDIM)   // 589824
#define CMAT (CDIM * CDIM)   // 65536

// Scratch layout (no cudaMalloc allowed)
#define OFF_A 0
#define OFF_Y ((size_t)CMAT * NB)
#define OFF_B (OFF_Y + (size_t)MAT * NB)
#define OFF_X (OFF_B + (size_t)CMAT * NB)
#define SCRATCH_FLOATS (OFF_X + (size_t)CMAT * NB)
__device__ float g_scratch[SCRATCH_FLOATS];

// ===========================================================================
// Helpers (baseline PTX only: ldmatrix sm_75+, mma.sync bf16 sm_80+)
// ===========================================================================
__device__ __forceinline__ uint32_t smem_to_u32(const void* p) {
    uint32_t a;
    asm("{ .reg .u64 t; cvta.to.shared.u64 t, %1; cvt.u32.u64 %0, t; }" : "=r"(a) : "l"(p));
    return a;
}
#define SMEM_SWIZZLE_128B(off) ((off) ^ (((off) >> 3) & 0x70))
#define STS128(r0, r1, r2, r3, addr) \
    asm volatile("st.shared.v4.b32 [%0], {%1, %2, %3, %4};" \
                 :: "r"(addr), "r"(r0), "r"(r1), "r"(r2), "r"(r3) : "memory")

__device__ __forceinline__ void ldsm_x4(uint32_t* r, uint32_t addr) {
    asm volatile("ldmatrix.sync.aligned.m8n8.x4.shared.b16 {%0,%1,%2,%3}, [%4];"
                 : "=r"(r[0]), "=r"(r[1]), "=r"(r[2]), "=r"(r[3]) : "r"(addr));
}
__device__ __forceinline__ void mma_bf16(float* d, const uint32_t* a, const uint32_t* b) {
    asm volatile(
        "mma.sync.aligned.m16n8k16.row.col.f32.bf16.bf16.f32 "
        "{%0,%1,%2,%3}, {%4,%5,%6,%7}, {%8,%9}, {%0,%1,%2,%3};"
        : "+f"(d[0]), "+f"(d[1]), "+f"(d[2]), "+f"(d[3])
        : "r"(a[0]), "r"(a[1]), "r"(a[2]), "r"(a[3]), "r"(b[0]), "r"(b[1]));
}

// ===========================================================================
// fp32 -> 2-limb bf16 conversion
// ===========================================================================
__device__ __forceinline__ uint32_t pack_bf16x2(float lo, float hi) {
    unsigned short a = __bfloat16_as_ushort(__float2bfloat16_rn(lo));
    unsigned short b = __bfloat16_as_ushort(__float2bfloat16_rn(hi));
    return ((uint32_t)b << 16) | (uint32_t)a;
}
__device__ __forceinline__ float bf_res(float v) {
    return v - __bfloat162float(__float2bfloat16_rn(v));
}

// Shared-memory layout: 4 tiles of [128 rows(M/N)][64 k] bf16, SW128 rows (128B).
#define SM_AHI   0
#define SM_ALO   16384
#define SM_BHI   32768
#define SM_BLO   49152
#define SMEM_DYN (65536 + 1024)   // + alignment slack

// Direct copy: gmem row-major [.. x ld], rows r0..r0+127, cols kt..kt+63
// -> tile[r][k] hi+lo limbs. float4 loads, coalesced.
__device__ __forceinline__ void conv_direct(const float* __restrict__ g, int ld,
                                            int r0, int kt,
                                            uint32_t smHi, uint32_t smLo, int tid) {
#pragma unroll
    for (int it = 0; it < 4; ++it) {
        int cell = tid + it * 256;           // 0..1023 : 128 rows x 8 k-groups
        int r = cell >> 3, kg = cell & 7;
        const float* p = g + (size_t)(r0 + r) * ld + kt + kg * 8;
        float4 v0 = *reinterpret_cast<const float4*>(p);
        float4 v1 = *reinterpret_cast<const float4*>(p + 4);
        float a[8] = {v0.x, v0.y, v0.z, v0.w, v1.x, v1.y, v1.z, v1.w};
        uint32_t h[4], l[4];
#pragma unroll
        for (int q = 0; q < 4; ++q) {
            h[q] = pack_bf16x2(a[2 * q], a[2 * q + 1]);
            l[q] = pack_bf16x2(bf_res(a[2 * q]), bf_res(a[2 * q + 1]));
        }
        uint32_t off = SMEM_SWIZZLE_128B((uint32_t)(r * 128 + kg * 16));
        STS128(h[0], h[1], h[2], h[3], smHi + off);
        STS128(l[0], l[1], l[2], l[3], smLo + off);
    }
}

// Transpose copy: gmem [rows x ld], k-rows kt..kt+63, cols c0..c0+127 (MN dim)
// -> tile[col][k]. Scalar loads coalesced across consecutive cols.
__device__ __forceinline__ void conv_transpose(const float* __restrict__ g, int ld,
                                               int kt, int c0,
                                               uint32_t smHi, uint32_t smLo, int tid) {
    int col = tid & 127;
    int ks = (tid >> 7) * 32;                 // 0 or 32
    const float* p = g + (size_t)(kt + ks) * ld + c0 + col;
    float v[32];
#pragma unroll
    for (int kk = 0; kk < 32; ++kk) v[kk] = p[(size_t)kk * ld];
#pragma unroll
    for (int g4 = 0; g4 < 4; ++g4) {
        uint32_t h[4], l[4];
#pragma unroll
        for (int q = 0; q < 4; ++q) {
            float x = v[g4 * 8 + 2 * q], y = v[g4 * 8 + 2 * q + 1];
            h[q] = pack_bf16x2(x, y);
            l[q] = pack_bf16x2(bf_res(x), bf_res(y));
        }
        uint32_t off = SMEM_SWIZZLE_128B((uint32_t)(col * 128 + ks * 2 + g4 * 16));
        STS128(h[0], h[1], h[2], h[3], smHi + off);
        STS128(l[0], l[1], l[2], l[3], smLo + off);
    }
}

// ===========================================================================
// Warp consumer: one K=64 chunk, 3 limb products, acc[4][4][4] (64x32 / warp)
// A tiles [m][k], B tiles [n][k]; ldmatrix non-trans for both (row.col mma).
// ===========================================================================
__device__ __forceinline__ void warp_consume(float (&acc)[4][4][4],
                                             uint32_t sAhi, uint32_t sAlo,
                                             uint32_t sBhi, uint32_t sBlo,
                                             int wm, int wn, int lane) {
#pragma unroll
    for (int kk = 0; kk < 4; ++kk) {
        uint32_t a[4][4], bh[4][2], bl[4][2];
        // A addresses: lane -> row (base + lane&15), k-half (lane>>4)
        uint32_t aoff[4];
#pragma unroll
        for (int mf = 0; mf < 4; ++mf) {
            uint32_t off = (uint32_t)((wm * 64 + mf * 16 + (lane & 15)) * 128
                                      + kk * 32 + ((lane >> 4) << 4));
            aoff[mf] = SMEM_SWIZZLE_128B(off);
            ldsm_x4(a[mf], sAhi + aoff[mf]);
        }
        // B addresses: lane groups of 8 -> (nfrag, khalf)
        uint32_t boff[2];
#pragma unroll
        for (int h = 0; h < 2; ++h) {
            uint32_t n = (uint32_t)(wn * 32 + h * 16 + ((lane >> 4) << 3) + (lane & 7));
            uint32_t off = n * 128 + kk * 32 + (((lane >> 3) & 1) << 4);
            boff[h] = SMEM_SWIZZLE_128B(off);
            ldsm_x4(&bh[h * 2][0], sBhi + boff[h]);
        }
        // hi * hi
#pragma unroll
        for (int mf = 0; mf < 4; ++mf)
#pragma unroll
            for (int nf = 0; nf < 4; ++nf)
                mma_bf16(acc[mf][nf], a[mf], bh[nf]);
        // hi * lo
#pragma unroll
        for (int h = 0; h < 2; ++h)
            ldsm_x4(&bl[h * 2][0], sBlo + boff[h]);
#pragma unroll
        for (int mf = 0; mf < 4; ++mf)
#pragma unroll
            for (int nf = 0; nf < 4; ++nf)
                mma_bf16(acc[mf][nf], a[mf], bl[nf]);
        // lo * hi  (reuse A registers)
#pragma unroll
        for (int mf = 0; mf < 4; ++mf)
            ldsm_x4(a[mf], sAlo + aoff[mf]);
#pragma unroll
        for (int mf = 0; mf < 4; ++mf)
#pragma unroll
            for (int nf = 0; nf < 4; ++nf)
                mma_bf16(acc[mf][nf], a[mf], bh[nf]);
    }
}

// ===========================================================================
// GEMM 1 & 3: O[p,q] = sum_r P[r,p] Q[r,q]  (256x256 out, K = 2304)
// grid = (2 q-tiles, 2 p-tiles, NB), 256 threads
// ===========================================================================
__global__ void __launch_bounds__(256, 2) gemm_AtB_mma(const float* __restrict__ Pg,
                                                       const float* __restrict__ Qg,
                                                       float* __restrict__ Og) {
    extern __shared__ char smem[];
    uint32_t sb = (smem_to_u32(smem) + 1023u) & ~1023u;
    int tid = threadIdx.x, lane = tid & 31, wid = tid >> 5;
    int wm = wid & 1, wn = wid >> 1;
    int b = blockIdx.z, q0 = blockIdx.x * 128, p0 = blockIdx.y * 128;
    const float* P = Pg + (size_t)b * MAT;
    const float* Q = Qg + (size_t)b * MAT;
    float* O = Og + (size_t)b * CMAT;

    float acc[4][4][4] = {};
    for (int kt = 0; kt < RDIM; kt += 64) {
        __syncthreads();
        conv_transpose(P, CDIM, kt, p0, sb + SM_AHI, sb + SM_ALO, tid);
        conv_transpose(Q, CDIM, kt, q0, sb + SM_BHI, sb + SM_BLO, tid);
        __syncthreads();
        warp_consume(acc, sb + SM_AHI, sb + SM_ALO, sb + SM_BHI, sb + SM_BLO,
                     wm, wn, lane);
    }
    int tr = lane >> 2, tc = (lane & 3) * 2;
#pragma unroll
    for (int mf = 0; mf < 4; ++mf)
#pragma unroll
        for (int nf = 0; nf < 4; ++nf) {
            int p = p0 + wm * 64 + mf * 16 + tr;
            int q = q0 + wn * 32 + nf * 8 + tc;
            *reinterpret_cast<float2*>(&O[(size_t)p * CDIM + q]) =
                make_float2(acc[mf][nf][0], acc[mf][nf][1]);
            *reinterpret_cast<float2*>(&O[(size_t)(p + 8) * CDIM + q]) =
                make_float2(acc[mf][nf][2], acc[mf][nf][3]);
        }
}

// ===========================================================================
// GEMM 2: Y = M - beta*(U+G) + beta*(M @ Asym)   grid = (2, 18, NB)
// B operand: Asym symmetric -> rows serve as K-major directly.
// ===========================================================================
__global__ void __launch_bounds__(256, 2) gemm_Y_mma(const float* __restrict__ Mg,
                                                     const float* __restrict__ Gg,
                                                     const float* __restrict__ Ug,
                                                     const float* __restrict__ lrg,
                                                     const float* __restrict__ slrg,
                                                     const float* __restrict__ Ag,
                                                     float* __restrict__ Yg) {
    extern __shared__ char smem[];
    uint32_t sb = (smem_to_u32(smem) + 1023u) & ~1023u;
    int tid = threadIdx.x, lane = tid & 31, wid = tid >> 5;
    int wm = wid & 1, wn = wid >> 1;
    int b = blockIdx.z, c0 = blockIdx.x * 128, r0 = blockIdx.y * 128;
    const float* M = Mg + (size_t)b * MAT;
    const float* G = Gg + (size_t)b * MAT;
    const float* U = Ug + (size_t)b * MAT;
    const float* Asym = Ag + (size_t)b * CMAT;
    float* Y = Yg + (size_t)b * MAT;
    float beta = fabsf(lrg[b]) * slrg[0];

    float acc[4][4][4] = {};
    for (int kt = 0; kt < CDIM; kt += 64) {
        __syncthreads();
        conv_direct(M, CDIM, r0, kt, sb + SM_AHI, sb + SM_ALO, tid);
        conv_direct(Asym, CDIM, c0, kt, sb + SM_BHI, sb + SM_BLO, tid);
        __syncthreads();
        warp_consume(acc, sb + SM_AHI, sb + SM_ALO, sb + SM_BHI, sb + SM_BLO,
                     wm, wn, lane);
    }
    int tr = lane >> 2, tc = (lane & 3) * 2;
#pragma unroll
    for (int mf = 0; mf < 4; ++mf)
#pragma unroll
        for (int nf = 0; nf < 4; ++nf) {
            int r = r0 + wm * 64 + mf * 16 + tr;
            int c = c0 + wn * 32 + nf * 8 + tc;
#pragma unroll
            for (int h = 0; h < 2; ++h) {
                size_t base = (size_t)(r + h * 8) * CDIM + c;
                float2 m = *reinterpret_cast<const float2*>(&M[base]);
                float2 g = *reinterpret_cast<const float2*>(&G[base]);
                float2 u = *reinterpret_cast<const float2*>(&U[base]);
                float2 o;
                o.x = m.x - beta * (u.x + g.x) + beta * acc[mf][nf][h * 2 + 0];
                o.y = m.y - beta * (u.y + g.y) + beta * acc[mf][nf][h * 2 + 1];
                *reinterpret_cast<float2*>(&Y[base]) = o;
            }
        }
}

// ===========================================================================
// GEMM 4: out[c,r] = sum_k Y[r,k] X[k,c]  (transposed store)  grid = (2,18,NB)
// ===========================================================================
__global__ void __launch_bounds__(256, 2) gemm_QT_mma(const float* __restrict__ Yg,
                                                      const float* __restrict__ Xg,
                                                      float* __restrict__ outg) {
    extern __shared__ char smem[];
    uint32_t sb = (smem_to_u32(smem) + 1023u) & ~1023u;
    int tid = threadIdx.x, lane = tid & 31, wid = tid >> 5;
    int wm = wid & 1, wn = wid >> 1;
    int b = blockIdx.z, c0 = blockIdx.x * 128, r0 = blockIdx.y * 128;
    const float* Y = Yg + (size_t)b * MAT;
    const float* X = Xg + (size_t)b * CMAT;
    float* O = outg + (size_t)b * MAT;    // [CDIM][RDIM]

    float acc[4][4][4] = {};
    for (int kt = 0; kt < CDIM; kt += 64) {
        __syncthreads();
        conv_direct(Y, CDIM, r0, kt, sb + SM_AHI, sb + SM_ALO, tid);
        conv_transpose(X, CDIM, kt, c0, sb + SM_BHI, sb + SM_BLO, tid);
        __syncthreads();
        warp_consume(acc, sb + SM_AHI, sb + SM_ALO, sb + SM_BHI, sb + SM_BLO,
                     wm, wn, lane);
    }
    int tr = lane >> 2, tc = (lane & 3) * 2;
#pragma unroll
    for (int mf = 0; mf < 4; ++mf)
#pragma unroll
        for (int nf = 0; nf < 4; ++nf) {
            int r = r0 + wm * 64 + mf * 16 + tr;
            int c = c0 + wn * 32 + nf * 8 + tc;
            O[(size_t)c * RDIM + r]           = acc[mf][nf][0];
            O[(size_t)(c + 1) * RDIM + r]     = acc[mf][nf][1];
            O[(size_t)c * RDIM + r + 8]       = acc[mf][nf][2];
            O[(size_t)(c + 1) * RDIM + r + 8] = acc[mf][nf][3];
        }
}

// ===========================================================================
// Symmetrize A in place: A <- 0.5 * (A + A^T)
// ===========================================================================
__global__ void sym_kernel(float* __restrict__ Ag) {
    float* A = Ag + (size_t)blockIdx.y * CMAT;
    int idx = blockIdx.x * blockDim.x + threadIdx.x;
    int i = idx >> 8, j = idx & 255;
    if (i < j) {
        float u = A[i * CDIM + j];
        float v = A[j * CDIM + i];
        float m = 0.5f * (u + v);
        A[i * CDIM + j] = m;
        A[j * CDIM + i] = m;
    }
}

// ===========================================================================
// Cholesky (upper, positive diag) of Bm = R^T R, then X = R^{-1}.
// One block (256 threads) per batch item; packed upper triangle in smem.
// ===========================================================================
__global__ void __launch_bounds__(256) cholinv_kernel(const float* __restrict__ Bg,
                                                      float* __restrict__ Xg) {
    extern __shared__ float sU[];   // packed upper: (i,j) i<=j at off(i) + j-i
    int b = blockIdx.x;
    const float* Bm = Bg + (size_t)b * CMAT;
    float* Xm = Xg + (size_t)b * CMAT;
    int tid = threadIdx.x;
    for (int i = 0; i < CDIM; ++i) {
        int o = i * CDIM - (i * (i - 1)) / 2;
        for (int j = i + tid; j < CDIM; j += 256)
            sU[o + (j - i)] = Bm[i * CDIM + j];
    }
    __syncthreads();
    int lane = tid & 31, warp = tid >> 5;
    for (int k = 0; k < CDIM; ++k) {
        int ok = k * CDIM - (k * (k - 1)) / 2;
        float inv = rsqrtf(sU[ok]);     // all read before any write
        __syncthreads();
        for (int j = k + tid; j < CDIM; j += 256)
            sU[ok + (j - k)] *= inv;
        __syncthreads();
        for (int i = k + 1 + warp; i < CDIM; i += 8) {
            float rki = sU[ok + (i - k)];
            int oi = i * CDIM - (i * (i - 1)) / 2;
            for (int j = i + lane; j < CDIM; j += 32)
                sU[oi + (j - i)] -= rki * sU[ok + (j - k)];
        }
        __syncthreads();
    }
    // triangular inverse: thread j owns column j of X = R^{-1}
    {
        int j = tid;
        float x[CDIM];
        int oj = j * CDIM - (j * (j - 1)) / 2;
        x[j] = 1.0f / sU[oj];
        for (int i = j - 1; i >= 0; --i) {
            int oi = i * CDIM - (i * (i - 1)) / 2;
            float s0 = 0.f, s1 = 0.f, s2 = 0.f, s3 = 0.f;
            int k = i + 1;
            for (; k + 3 <= j; k += 4) {
                s0 += sU[oi + (k - i)]     * x[k];
                s1 += sU[oi + (k + 1 - i)] * x[k + 1];
                s2 += sU[oi + (k + 2 - i)] * x[k + 2];
                s3 += sU[oi + (k + 3 - i)] * x[k + 3];
            }
            for (; k <= j; ++k) s0 += sU[oi + (k - i)] * x[k];
            x[i] = -((s0 + s1) + (s2 + s3)) / sU[oi];
        }
        for (int i = 0; i < CDIM; ++i)
            Xm[(size_t)i * CDIM + j] = (i <= j) ? x[i] : 0.0f;
    }
}

// ===========================================================================
// Launch
// ===========================================================================
extern "C" void kernel_launch(void* const* d_in, const int* in_sizes, int n_in,
                              void* d_out, int out_size) {
    const float* M   = (const float*)d_in[0];
    const float* G   = (const float*)d_in[1];
    const float* U   = (const float*)d_in[2];
    const float* lr  = (const float*)d_in[3];
    const float* slr = (const float*)d_in[4];
    float* out = (float*)d_out;

    float* scratch = nullptr;
    cudaGetSymbolAddress((void**)&scratch, g_scratch);
    float* A  = scratch + OFF_A;
    float* Y  = scratch + OFF_Y;
    float* Bm = scratch + OFF_B;
    float* X  = scratch + OFF_X;

    const int TRI_BYTES = (CDIM * (CDIM + 1) / 2) * (int)sizeof(float);  // 131584
    cudaFuncSetAttribute(gemm_AtB_mma, cudaFuncAttributeMaxDynamicSharedMemorySize, SMEM_DYN);
    cudaFuncSetAttribute(gemm_Y_mma,   cudaFuncAttributeMaxDynamicSharedMemorySize, SMEM_DYN);
    cudaFuncSetAttribute(gemm_QT_mma,  cudaFuncAttributeMaxDynamicSharedMemorySize, SMEM_DYN);
    cudaFuncSetAttribute(cholinv_kernel, cudaFuncAttributeMaxDynamicSharedMemorySize, TRI_BYTES);

    // 1) A = M^T G
    gemm_AtB_mma<<<dim3(2, 2, NB), 256, SMEM_DYN>>>(M, G, A);
    // 2) A <- sym(A)
    sym_kernel<<<dim3(CMAT / 256, NB), 256>>>(A);
    // 3) Y = M - beta*(U+G) + beta*M*Asym
    gemm_Y_mma<<<dim3(2, RDIM / 128, NB), 256, SMEM_DYN>>>(M, G, U, lr, slr, A, Y);
    // 4) Bm = Y^T Y
    gemm_AtB_mma<<<dim3(2, 2, NB), 256, SMEM_DYN>>>(Y, Y, Bm);
    // 5) R = chol(Bm), X = R^{-1}
    cholinv_kernel<<<NB, 256, TRI_BYTES>>>(Bm, X);
    // 6) out = (Y X)^T
    gemm_QT_mma<<<dim3(2, RDIM / 128, NB), 256, SMEM_DYN>>>(Y, X, out);
}